// round 2
// baseline (speedup 1.0000x reference)
#include <cuda_runtime.h>

#define NNODES 100000
#define NEDGES 1600000
#define DF 128
#define NCLS 40
#define TM 64
#define TLD 132   // padded tile stride (floats)
#define FTM 64

// Scratch (allocation-free rule: __device__ globals)
__device__ float g_agg[NNODES * DF];
__device__ float g_h1[NNODES * DF];
__device__ float g_h2[NNODES * DF];
__device__ int   g_src[NEDGES];
__device__ int   g_dst[NEDGES];

// ---------------------------------------------------------------------------
// Canonicalize edge_index into int32 src/dst, handling both int32 and int64
// source layouts. If the buffer is int64 (values < 100000, non-negative),
// every odd int32 word of the first 16 is zero; for real int32 edge data the
// chance of that is ~1e-40.
__global__ void convert_edges_kernel(const int* __restrict__ raw,
                                     int* __restrict__ src,
                                     int* __restrict__ dst) {
    bool is64 = (raw[1] | raw[3] | raw[5] | raw[7] |
                 raw[9] | raw[11] | raw[13] | raw[15]) == 0;
    int i = blockIdx.x * blockDim.x + threadIdx.x;
    if (i >= NEDGES) return;
    if (is64) {
        src[i] = raw[2 * i];
        dst[i] = raw[2 * NEDGES + 2 * i];
    } else {
        src[i] = raw[i];
        dst[i] = raw[NEDGES + i];
    }
}

// ---------------------------------------------------------------------------
__global__ void zero_kernel(float4* __restrict__ p, int n4) {
    int i = blockIdx.x * blockDim.x + threadIdx.x;
    if (i < n4) p[i] = make_float4(0.f, 0.f, 0.f, 0.f);
}

// ---------------------------------------------------------------------------
// Warp per edge: 32 lanes x float4 = 512B row. Gather feat[src], atomic-add
// into agg[dst]. Both buffers are L2-resident (51MB each).
__global__ void edge_agg_kernel(const float* __restrict__ feat,
                                const int* __restrict__ srcs,
                                const int* __restrict__ dsts,
                                float* __restrict__ agg) {
    int gw = (blockIdx.x * blockDim.x + threadIdx.x) >> 5;
    int lane = threadIdx.x & 31;
    if (gw >= NEDGES) return;
    int s = 0, d = 0;
    if (lane == 0) { s = __ldg(srcs + gw); d = __ldg(dsts + gw); }
    s = __shfl_sync(0xffffffffu, s, 0);
    d = __shfl_sync(0xffffffffu, d, 0);
    float4 v = *reinterpret_cast<const float4*>(feat + (size_t)s * DF + lane * 4);
    float* a = agg + (size_t)d * DF + lane * 4;
    atomicAdd(a + 0, v.x);
    atomicAdd(a + 1, v.y);
    atomicAdd(a + 2, v.z);
    atomicAdd(a + 3, v.w);
}

// ---------------------------------------------------------------------------
// Fused GIN MLP: out = relu( relu( (x+agg) @ wa + ba ) @ wb + bb )
// 64-row tile per block, both 128x128 weights in smem, intermediate in smem.
__global__ __launch_bounds__(256, 1)
void mlp_kernel(const float* __restrict__ xin, const float* __restrict__ agg,
                const float* __restrict__ wa, const float* __restrict__ ba,
                const float* __restrict__ wb, const float* __restrict__ bb,
                float* __restrict__ out, int relu_out) {
    extern __shared__ float sm[];
    float* ws_a  = sm;                    // 128*128
    float* ws_b  = sm + DF * DF;          // 128*128
    float* tile  = sm + 2 * DF * DF;      // TM*TLD
    float* htile = tile + TM * TLD;       // TM*TLD

    const int t = threadIdx.x;
    const int row0 = blockIdx.x * TM;

    // Load both weight matrices (k-major: w[k*128 + n])
    {
        const float4* wa4 = reinterpret_cast<const float4*>(wa);
        const float4* wb4 = reinterpret_cast<const float4*>(wb);
        float4* wsa4 = reinterpret_cast<float4*>(ws_a);
        float4* wsb4 = reinterpret_cast<float4*>(ws_b);
#pragma unroll
        for (int i = 0; i < (DF * DF / 4) / 256; i++) {   // 16 iters
            wsa4[t + i * 256] = wa4[t + i * 256];
            wsb4[t + i * 256] = wb4[t + i * 256];
        }
    }

    // Load input tile: tile[r][k] = x[gr][k] + agg[gr][k]
    {
        int c4 = t & 31;   // float4 column
        int rr = t >> 5;   // 0..7
#pragma unroll
        for (int i = 0; i < TM / 8; i++) {
            int r = rr + i * 8;
            int gr = row0 + r;
            float4 v = make_float4(0.f, 0.f, 0.f, 0.f);
            if (gr < NNODES) {
                float4 xv = reinterpret_cast<const float4*>(xin + (size_t)gr * DF)[c4];
                float4 av = reinterpret_cast<const float4*>(agg + (size_t)gr * DF)[c4];
                v = make_float4(xv.x + av.x, xv.y + av.y, xv.z + av.z, xv.w + av.w);
            }
            *reinterpret_cast<float4*>(&tile[r * TLD + c4 * 4]) = v;
        }
    }
    __syncthreads();

    const int tx = t & 15;          // 16 column groups of 8
    const int ty = t >> 4;          // 16 row groups of 4
    const int col = tx * 8;

    float acc[4][8];

    // ---- GEMM 1: h = relu(tile @ wa + ba) ----
    {
        float4 bv0 = *reinterpret_cast<const float4*>(ba + col);
        float4 bv1 = *reinterpret_cast<const float4*>(ba + col + 4);
        float bj[8] = {bv0.x, bv0.y, bv0.z, bv0.w, bv1.x, bv1.y, bv1.z, bv1.w};
#pragma unroll
        for (int i = 0; i < 4; i++)
#pragma unroll
            for (int j = 0; j < 8; j++) acc[i][j] = bj[j];
    }
#pragma unroll 8
    for (int k = 0; k < DF; k++) {
        float aa[4];
#pragma unroll
        for (int i = 0; i < 4; i++) aa[i] = tile[(ty * 4 + i) * TLD + k];
        float4 b0 = *reinterpret_cast<const float4*>(&ws_a[k * DF + col]);
        float4 b1 = *reinterpret_cast<const float4*>(&ws_a[k * DF + col + 4]);
        float bb_[8] = {b0.x, b0.y, b0.z, b0.w, b1.x, b1.y, b1.z, b1.w};
#pragma unroll
        for (int i = 0; i < 4; i++)
#pragma unroll
            for (int j = 0; j < 8; j++) acc[i][j] += aa[i] * bb_[j];
    }
#pragma unroll
    for (int i = 0; i < 4; i++) {
        float4 h0 = make_float4(fmaxf(acc[i][0], 0.f), fmaxf(acc[i][1], 0.f),
                                fmaxf(acc[i][2], 0.f), fmaxf(acc[i][3], 0.f));
        float4 h1 = make_float4(fmaxf(acc[i][4], 0.f), fmaxf(acc[i][5], 0.f),
                                fmaxf(acc[i][6], 0.f), fmaxf(acc[i][7], 0.f));
        *reinterpret_cast<float4*>(&htile[(ty * 4 + i) * TLD + col]) = h0;
        *reinterpret_cast<float4*>(&htile[(ty * 4 + i) * TLD + col + 4]) = h1;
    }
    __syncthreads();

    // ---- GEMM 2: out = maybe_relu(h @ wb + bb) ----
    {
        float4 bv0 = *reinterpret_cast<const float4*>(bb + col);
        float4 bv1 = *reinterpret_cast<const float4*>(bb + col + 4);
        float bj[8] = {bv0.x, bv0.y, bv0.z, bv0.w, bv1.x, bv1.y, bv1.z, bv1.w};
#pragma unroll
        for (int i = 0; i < 4; i++)
#pragma unroll
            for (int j = 0; j < 8; j++) acc[i][j] = bj[j];
    }
#pragma unroll 8
    for (int k = 0; k < DF; k++) {
        float aa[4];
#pragma unroll
        for (int i = 0; i < 4; i++) aa[i] = htile[(ty * 4 + i) * TLD + k];
        float4 b0 = *reinterpret_cast<const float4*>(&ws_b[k * DF + col]);
        float4 b1 = *reinterpret_cast<const float4*>(&ws_b[k * DF + col + 4]);
        float bb_[8] = {b0.x, b0.y, b0.z, b0.w, b1.x, b1.y, b1.z, b1.w};
#pragma unroll
        for (int i = 0; i < 4; i++)
#pragma unroll
            for (int j = 0; j < 8; j++) acc[i][j] += aa[i] * bb_[j];
    }
#pragma unroll
    for (int i = 0; i < 4; i++) {
        int gr = row0 + ty * 4 + i;
        if (gr >= NNODES) continue;
        float v[8];
#pragma unroll
        for (int j = 0; j < 8; j++)
            v[j] = relu_out ? fmaxf(acc[i][j], 0.f) : acc[i][j];
        float4 o0 = make_float4(v[0], v[1], v[2], v[3]);
        float4 o1 = make_float4(v[4], v[5], v[6], v[7]);
        *reinterpret_cast<float4*>(out + (size_t)gr * DF + col) = o0;
        *reinterpret_cast<float4*>(out + (size_t)gr * DF + col + 4) = o1;
    }
}

// ---------------------------------------------------------------------------
// Final FC (128 -> 40) + log_softmax, fused. 320 threads, 64 rows per block.
__global__ __launch_bounds__(320, 1)
void fc_softmax_kernel(const float* __restrict__ h, const float* __restrict__ wfc,
                       const float* __restrict__ bfc, float* __restrict__ out) {
    extern __shared__ float sm[];
    float* wsm   = sm;                         // DF*NCLS = 5120
    float* tile  = sm + DF * NCLS;             // FTM*DF  = 8192
    float* lg    = tile + FTM * DF;            // FTM*NCLS = 2560
    float* rstat = lg + FTM * NCLS;            // 2*FTM
    __shared__ float bsm[NCLS];

    const int t = threadIdx.x;
    const int row0 = blockIdx.x * FTM;

    for (int i = t; i < DF * NCLS; i += 320) wsm[i] = wfc[i];
    if (t < NCLS) bsm[t] = bfc[t];
    for (int i = t; i < FTM * DF / 4; i += 320) {
        int r = i >> 5;           // 32 float4 per row
        int c4 = i & 31;
        int gr = row0 + r;
        float4 v = (gr < NNODES)
                       ? reinterpret_cast<const float4*>(h + (size_t)gr * DF)[c4]
                       : make_float4(0.f, 0.f, 0.f, 0.f);
        reinterpret_cast<float4*>(tile)[i] = v;
    }
    __syncthreads();

    // thread -> (row, 8-class group): r = t/5, cg = t%5
    const int r = t / 5;
    const int cg = t % 5;
    const int cb = cg * 8;
    float acc[8];
#pragma unroll
    for (int j = 0; j < 8; j++) acc[j] = bsm[cb + j];
#pragma unroll 4
    for (int k = 0; k < DF; k++) {
        float a = tile[r * DF + k];
        float4 w0 = *reinterpret_cast<const float4*>(&wsm[k * NCLS + cb]);
        float4 w1 = *reinterpret_cast<const float4*>(&wsm[k * NCLS + cb + 4]);
        acc[0] += a * w0.x; acc[1] += a * w0.y; acc[2] += a * w0.z; acc[3] += a * w0.w;
        acc[4] += a * w1.x; acc[5] += a * w1.y; acc[6] += a * w1.z; acc[7] += a * w1.w;
    }
#pragma unroll
    for (int j = 0; j < 8; j++) lg[r * NCLS + cb + j] = acc[j];
    __syncthreads();

    if (t < FTM) {
        float m = -1e30f;
#pragma unroll
        for (int c = 0; c < NCLS; c++) m = fmaxf(m, lg[t * NCLS + c]);
        float s = 0.f;
#pragma unroll
        for (int c = 0; c < NCLS; c++) s += expf(lg[t * NCLS + c] - m);
        rstat[t] = m;
        rstat[FTM + t] = logf(s);
    }
    __syncthreads();

    int gr = row0 + r;
    if (gr < NNODES) {
        float m = rstat[r], ls = rstat[FTM + r];
#pragma unroll
        for (int j = 0; j < 8; j++)
            out[(size_t)gr * NCLS + cb + j] = lg[r * NCLS + cb + j] - m - ls;
    }
}

// ---------------------------------------------------------------------------
extern "C" void kernel_launch(void* const* d_in, const int* in_sizes, int n_in,
                              void* d_out, int out_size) {
    const float* x        = (const float*)d_in[0];
    const int*   ei_raw   = (const int*)d_in[1];
    const float* w1a      = (const float*)d_in[2];
    const float* b1a      = (const float*)d_in[3];
    const float* w1b      = (const float*)d_in[4];
    const float* b1b      = (const float*)d_in[5];
    const float* w2a      = (const float*)d_in[6];
    const float* b2a      = (const float*)d_in[7];
    const float* w2b      = (const float*)d_in[8];
    const float* b2b      = (const float*)d_in[9];
    const float* wfc      = (const float*)d_in[10];
    const float* bfc      = (const float*)d_in[11];
    float* out            = (float*)d_out;

    float *agg, *h1, *h2;
    int *src, *dst;
    cudaGetSymbolAddress((void**)&agg, g_agg);
    cudaGetSymbolAddress((void**)&h1, g_h1);
    cudaGetSymbolAddress((void**)&h2, g_h2);
    cudaGetSymbolAddress((void**)&src, g_src);
    cudaGetSymbolAddress((void**)&dst, g_dst);

    const size_t mlp_smem = (size_t)(2 * DF * DF + 2 * TM * TLD) * sizeof(float);
    const size_t fc_smem  = (size_t)(DF * NCLS + FTM * DF + FTM * NCLS + 2 * FTM) * sizeof(float);
    cudaFuncSetAttribute(mlp_kernel, cudaFuncAttributeMaxDynamicSharedMemorySize, (int)mlp_smem);
    cudaFuncSetAttribute(fc_softmax_kernel, cudaFuncAttributeMaxDynamicSharedMemorySize, (int)fc_smem);

    const int n4 = NNODES * DF / 4;
    const int zgrid = (n4 + 255) / 256;
    const int egrid = (int)(((long long)NEDGES * 32 + 255) / 256);
    const int cgrid = (NEDGES + 255) / 256;
    const int mgrid = (NNODES + TM - 1) / TM;

    convert_edges_kernel<<<cgrid, 256>>>(ei_raw, src, dst);

    // Layer 1
    zero_kernel<<<zgrid, 256>>>((float4*)agg, n4);
    edge_agg_kernel<<<egrid, 256>>>(x, src, dst, agg);
    mlp_kernel<<<mgrid, 256, mlp_smem>>>(x, agg, w1a, b1a, w1b, b1b, h1, 1);
    // Layer 2
    zero_kernel<<<zgrid, 256>>>((float4*)agg, n4);
    edge_agg_kernel<<<egrid, 256>>>(h1, src, dst, agg);
    mlp_kernel<<<mgrid, 256, mlp_smem>>>(h1, agg, w2a, b2a, w2b, b2b, h2, 1);
    // Head
    fc_softmax_kernel<<<mgrid, 320, fc_smem>>>(h2, wfc, bfc, out);
}

// round 3
// speedup vs baseline: 1.6487x; 1.6487x over previous
#include <cuda_runtime.h>

#define NNODES 100000
#define NEDGES 1600000
#define DF 128
#define NCLS 40
#define TM 64
#define TLD 132   // padded tile stride (floats)
#define FTM 64
#define SCAN_T 1024
#define SCAN_CHUNK ((NNODES + SCAN_T - 1) / SCAN_T)   // 98

// Scratch (allocation-free rule: __device__ globals)
__device__ float g_pre[NNODES * DF];   // x + agg (layer input to MLP)
__device__ float g_h1[NNODES * DF];
__device__ float g_h2[NNODES * DF];
__device__ int   g_src[NEDGES];
__device__ int   g_dst[NEDGES];
__device__ int   g_csr[NEDGES];        // src sorted by dst
__device__ int   g_deg[NNODES];
__device__ int   g_off[NNODES + 1];
__device__ int   g_cur[NNODES];

// ---- packed f32x2 helpers ---------------------------------------------------
__device__ __forceinline__ unsigned long long pack2(float x, float y) {
    unsigned long long r;
    asm("mov.b64 %0, {%1,%2};" : "=l"(r)
        : "r"(__float_as_uint(x)), "r"(__float_as_uint(y)));
    return r;
}
__device__ __forceinline__ unsigned long long packdup(float x) {
    unsigned long long r;
    asm("mov.b64 %0, {%1,%1};" : "=l"(r) : "r"(__float_as_uint(x)));
    return r;
}
#define FMA2(d, a, b, c) \
    asm("fma.rn.f32x2 %0, %1, %2, %3;" : "=l"(d) : "l"(a), "l"(b), "l"(c))

// ---------------------------------------------------------------------------
__global__ void zero_int_kernel(int* __restrict__ p, int n) {
    int i = blockIdx.x * blockDim.x + threadIdx.x;
    if (i < n) p[i] = 0;
}

// Canonicalize edges (int32 vs int64 robust) + degree histogram by dst.
__global__ void build_edges_kernel(const int* __restrict__ raw,
                                   int* __restrict__ src,
                                   int* __restrict__ dst,
                                   int* __restrict__ deg) {
    bool is64 = (raw[1] | raw[3] | raw[5] | raw[7] |
                 raw[9] | raw[11] | raw[13] | raw[15]) == 0;
    int i = blockIdx.x * blockDim.x + threadIdx.x;
    if (i >= NEDGES) return;
    int s, d;
    if (is64) { s = raw[2 * i]; d = raw[2 * NEDGES + 2 * i]; }
    else      { s = raw[i];     d = raw[NEDGES + i]; }
    src[i] = s;
    dst[i] = d;
    atomicAdd(deg + d, 1);
}

// Single-block exclusive scan of degrees -> offsets (+ cursor copy).
__global__ __launch_bounds__(SCAN_T, 1)
void scan_kernel(const int* __restrict__ deg, int* __restrict__ off,
                 int* __restrict__ cur) {
    __shared__ int s[SCAN_T];
    int t = threadIdx.x;
    int base = t * SCAN_CHUNK;
    int sum = 0;
    for (int i = 0; i < SCAN_CHUNK; i++) {
        int idx = base + i;
        if (idx < NNODES) sum += deg[idx];
    }
    s[t] = sum;
    __syncthreads();
    for (int ofs = 1; ofs < SCAN_T; ofs <<= 1) {
        int v = (t >= ofs) ? s[t - ofs] : 0;
        __syncthreads();
        s[t] += v;
        __syncthreads();
    }
    int run = (t == 0) ? 0 : s[t - 1];
    for (int i = 0; i < SCAN_CHUNK; i++) {
        int idx = base + i;
        if (idx < NNODES) {
            off[idx] = run;
            cur[idx] = run;
            run += deg[idx];
        }
    }
    if (t == 0) off[NNODES] = s[SCAN_T - 1];
}

__global__ void scatter_kernel(const int* __restrict__ src,
                               const int* __restrict__ dst,
                               int* __restrict__ cur,
                               int* __restrict__ csr) {
    int i = blockIdx.x * blockDim.x + threadIdx.x;
    if (i >= NEDGES) return;
    int pos = atomicAdd(cur + dst[i], 1);
    csr[pos] = src[i];
}

// ---------------------------------------------------------------------------
// Gather aggregation, no atomics: pre[node] = xin[node] + sum_{nbr} feat[nbr].
// Warp per node, 32 lanes x float4 = 512B row, accumulate in registers.
__global__ void agg_kernel(const float* __restrict__ feat,
                           const float* __restrict__ xin,
                           const int* __restrict__ off,
                           const int* __restrict__ csr,
                           float* __restrict__ pre) {
    int node = (blockIdx.x * blockDim.x + threadIdx.x) >> 5;
    int lane = threadIdx.x & 31;
    if (node >= NNODES) return;
    int e0 = off[node], e1 = off[node + 1];
    float4 acc = reinterpret_cast<const float4*>(xin + (size_t)node * DF)[lane];
    int e = e0;
#pragma unroll 1
    for (; e + 4 <= e1; e += 4) {
        int n0 = __ldg(csr + e), n1 = __ldg(csr + e + 1);
        int n2 = __ldg(csr + e + 2), n3 = __ldg(csr + e + 3);
        float4 v0 = *reinterpret_cast<const float4*>(feat + (size_t)n0 * DF + lane * 4);
        float4 v1 = *reinterpret_cast<const float4*>(feat + (size_t)n1 * DF + lane * 4);
        float4 v2 = *reinterpret_cast<const float4*>(feat + (size_t)n2 * DF + lane * 4);
        float4 v3 = *reinterpret_cast<const float4*>(feat + (size_t)n3 * DF + lane * 4);
        acc.x += v0.x + v1.x + v2.x + v3.x;
        acc.y += v0.y + v1.y + v2.y + v3.y;
        acc.z += v0.z + v1.z + v2.z + v3.z;
        acc.w += v0.w + v1.w + v2.w + v3.w;
    }
    for (; e < e1; e++) {
        int n0 = __ldg(csr + e);
        float4 v0 = *reinterpret_cast<const float4*>(feat + (size_t)n0 * DF + lane * 4);
        acc.x += v0.x; acc.y += v0.y; acc.z += v0.z; acc.w += v0.w;
    }
    *reinterpret_cast<float4*>(pre + (size_t)node * DF + lane * 4) = acc;
}

// ---------------------------------------------------------------------------
// Fused GIN MLP with packed f32x2 FMA:
// out = relu( relu( pre @ wa + ba ) @ wb + bb )
__global__ __launch_bounds__(256, 1)
void mlp_kernel(const float* __restrict__ pre,
                const float* __restrict__ wa, const float* __restrict__ ba,
                const float* __restrict__ wb, const float* __restrict__ bb,
                float* __restrict__ out) {
    extern __shared__ float sm[];
    float* ws_a  = sm;                    // 128*128
    float* ws_b  = sm + DF * DF;          // 128*128
    float* tile  = sm + 2 * DF * DF;      // TM*TLD
    float* htile = tile + TM * TLD;       // TM*TLD

    const int t = threadIdx.x;
    const int row0 = blockIdx.x * TM;

    // Load both weight matrices (k-major: w[k*128 + n])
    {
        const float4* wa4 = reinterpret_cast<const float4*>(wa);
        const float4* wb4 = reinterpret_cast<const float4*>(wb);
        float4* wsa4 = reinterpret_cast<float4*>(ws_a);
        float4* wsb4 = reinterpret_cast<float4*>(ws_b);
#pragma unroll
        for (int i = 0; i < (DF * DF / 4) / 256; i++) {
            wsa4[t + i * 256] = wa4[t + i * 256];
            wsb4[t + i * 256] = wb4[t + i * 256];
        }
    }

    // Load input tile
    {
        int c4 = t & 31;
        int rr = t >> 5;
#pragma unroll
        for (int i = 0; i < TM / 8; i++) {
            int r = rr + i * 8;
            int gr = row0 + r;
            float4 v = make_float4(0.f, 0.f, 0.f, 0.f);
            if (gr < NNODES)
                v = reinterpret_cast<const float4*>(pre + (size_t)gr * DF)[c4];
            *reinterpret_cast<float4*>(&tile[r * TLD + c4 * 4]) = v;
        }
    }
    __syncthreads();

    const int tx = t & 15;          // 16 column groups of 8
    const int ty = t >> 4;          // 16 row groups of 4
    const int col = tx * 8;

    unsigned long long acc[4][4];   // 4 rows x 4 packed pairs (8 cols)

    // ---- GEMM 1: h = relu(tile @ wa + ba) ----
    {
        float4 bv0 = *reinterpret_cast<const float4*>(ba + col);
        float4 bv1 = *reinterpret_cast<const float4*>(ba + col + 4);
        unsigned long long bp[4] = {pack2(bv0.x, bv0.y), pack2(bv0.z, bv0.w),
                                    pack2(bv1.x, bv1.y), pack2(bv1.z, bv1.w)};
#pragma unroll
        for (int i = 0; i < 4; i++)
#pragma unroll
            for (int j = 0; j < 4; j++) acc[i][j] = bp[j];
    }
#pragma unroll 8
    for (int k = 0; k < DF; k++) {
        unsigned long long aap[4];
#pragma unroll
        for (int i = 0; i < 4; i++) aap[i] = packdup(tile[(ty * 4 + i) * TLD + k]);
        ulonglong2 q0 = *reinterpret_cast<const ulonglong2*>(&ws_a[k * DF + col]);
        ulonglong2 q1 = *reinterpret_cast<const ulonglong2*>(&ws_a[k * DF + col + 4]);
        unsigned long long bp[4] = {q0.x, q0.y, q1.x, q1.y};
#pragma unroll
        for (int i = 0; i < 4; i++)
#pragma unroll
            for (int j = 0; j < 4; j++) FMA2(acc[i][j], aap[i], bp[j], acc[i][j]);
    }
#pragma unroll
    for (int i = 0; i < 4; i++) {
        float v[8];
#pragma unroll
        for (int j = 0; j < 4; j++) {
            uint2 u = *reinterpret_cast<uint2*>(&acc[i][j]);
            v[2 * j]     = fmaxf(__uint_as_float(u.x), 0.f);
            v[2 * j + 1] = fmaxf(__uint_as_float(u.y), 0.f);
        }
        *reinterpret_cast<float4*>(&htile[(ty * 4 + i) * TLD + col]) =
            make_float4(v[0], v[1], v[2], v[3]);
        *reinterpret_cast<float4*>(&htile[(ty * 4 + i) * TLD + col + 4]) =
            make_float4(v[4], v[5], v[6], v[7]);
    }
    __syncthreads();

    // ---- GEMM 2: out = relu(h @ wb + bb) ----
    {
        float4 bv0 = *reinterpret_cast<const float4*>(bb + col);
        float4 bv1 = *reinterpret_cast<const float4*>(bb + col + 4);
        unsigned long long bp[4] = {pack2(bv0.x, bv0.y), pack2(bv0.z, bv0.w),
                                    pack2(bv1.x, bv1.y), pack2(bv1.z, bv1.w)};
#pragma unroll
        for (int i = 0; i < 4; i++)
#pragma unroll
            for (int j = 0; j < 4; j++) acc[i][j] = bp[j];
    }
#pragma unroll 8
    for (int k = 0; k < DF; k++) {
        unsigned long long aap[4];
#pragma unroll
        for (int i = 0; i < 4; i++) aap[i] = packdup(htile[(ty * 4 + i) * TLD + k]);
        ulonglong2 q0 = *reinterpret_cast<const ulonglong2*>(&ws_b[k * DF + col]);
        ulonglong2 q1 = *reinterpret_cast<const ulonglong2*>(&ws_b[k * DF + col + 4]);
        unsigned long long bp[4] = {q0.x, q0.y, q1.x, q1.y};
#pragma unroll
        for (int i = 0; i < 4; i++)
#pragma unroll
            for (int j = 0; j < 4; j++) FMA2(acc[i][j], aap[i], bp[j], acc[i][j]);
    }
#pragma unroll
    for (int i = 0; i < 4; i++) {
        int gr = row0 + ty * 4 + i;
        if (gr >= NNODES) continue;
        float v[8];
#pragma unroll
        for (int j = 0; j < 4; j++) {
            uint2 u = *reinterpret_cast<uint2*>(&acc[i][j]);
            v[2 * j]     = fmaxf(__uint_as_float(u.x), 0.f);
            v[2 * j + 1] = fmaxf(__uint_as_float(u.y), 0.f);
        }
        *reinterpret_cast<float4*>(out + (size_t)gr * DF + col) =
            make_float4(v[0], v[1], v[2], v[3]);
        *reinterpret_cast<float4*>(out + (size_t)gr * DF + col + 4) =
            make_float4(v[4], v[5], v[6], v[7]);
    }
}

// ---------------------------------------------------------------------------
// Final FC (128 -> 40) + log_softmax, fused. 320 threads, 64 rows per block.
__global__ __launch_bounds__(320, 1)
void fc_softmax_kernel(const float* __restrict__ h, const float* __restrict__ wfc,
                       const float* __restrict__ bfc, float* __restrict__ out) {
    extern __shared__ float sm[];
    float* wsm   = sm;                         // DF*NCLS = 5120
    float* tile  = sm + DF * NCLS;             // FTM*DF  = 8192
    float* lg    = tile + FTM * DF;            // FTM*NCLS = 2560
    float* rstat = lg + FTM * NCLS;            // 2*FTM
    __shared__ float bsm[NCLS];

    const int t = threadIdx.x;
    const int row0 = blockIdx.x * FTM;

    for (int i = t; i < DF * NCLS; i += 320) wsm[i] = wfc[i];
    if (t < NCLS) bsm[t] = bfc[t];
    for (int i = t; i < FTM * DF / 4; i += 320) {
        int r = i >> 5;
        int c4 = i & 31;
        int gr = row0 + r;
        float4 v = (gr < NNODES)
                       ? reinterpret_cast<const float4*>(h + (size_t)gr * DF)[c4]
                       : make_float4(0.f, 0.f, 0.f, 0.f);
        reinterpret_cast<float4*>(tile)[i] = v;
    }
    __syncthreads();

    const int r = t / 5;
    const int cg = t % 5;
    const int cb = cg * 8;
    float acc[8];
#pragma unroll
    for (int j = 0; j < 8; j++) acc[j] = bsm[cb + j];
#pragma unroll 4
    for (int k = 0; k < DF; k++) {
        float a = tile[r * DF + k];
        float4 w0 = *reinterpret_cast<const float4*>(&wsm[k * NCLS + cb]);
        float4 w1 = *reinterpret_cast<const float4*>(&wsm[k * NCLS + cb + 4]);
        acc[0] += a * w0.x; acc[1] += a * w0.y; acc[2] += a * w0.z; acc[3] += a * w0.w;
        acc[4] += a * w1.x; acc[5] += a * w1.y; acc[6] += a * w1.z; acc[7] += a * w1.w;
    }
#pragma unroll
    for (int j = 0; j < 8; j++) lg[r * NCLS + cb + j] = acc[j];
    __syncthreads();

    if (t < FTM) {
        float m = -1e30f;
#pragma unroll
        for (int c = 0; c < NCLS; c++) m = fmaxf(m, lg[t * NCLS + c]);
        float s = 0.f;
#pragma unroll
        for (int c = 0; c < NCLS; c++) s += expf(lg[t * NCLS + c] - m);
        rstat[t] = m;
        rstat[FTM + t] = logf(s);
    }
    __syncthreads();

    int gr = row0 + r;
    if (gr < NNODES) {
        float m = rstat[r], ls = rstat[FTM + r];
#pragma unroll
        for (int j = 0; j < 8; j++)
            out[(size_t)gr * NCLS + cb + j] = lg[r * NCLS + cb + j] - m - ls;
    }
}

// ---------------------------------------------------------------------------
extern "C" void kernel_launch(void* const* d_in, const int* in_sizes, int n_in,
                              void* d_out, int out_size) {
    const float* x        = (const float*)d_in[0];
    const int*   ei_raw   = (const int*)d_in[1];
    const float* w1a      = (const float*)d_in[2];
    const float* b1a      = (const float*)d_in[3];
    const float* w1b      = (const float*)d_in[4];
    const float* b1b      = (const float*)d_in[5];
    const float* w2a      = (const float*)d_in[6];
    const float* b2a      = (const float*)d_in[7];
    const float* w2b      = (const float*)d_in[8];
    const float* b2b      = (const float*)d_in[9];
    const float* wfc      = (const float*)d_in[10];
    const float* bfc      = (const float*)d_in[11];
    float* out            = (float*)d_out;

    float *pre, *h1, *h2;
    int *src, *dst, *csr, *deg, *off, *cur;
    cudaGetSymbolAddress((void**)&pre, g_pre);
    cudaGetSymbolAddress((void**)&h1, g_h1);
    cudaGetSymbolAddress((void**)&h2, g_h2);
    cudaGetSymbolAddress((void**)&src, g_src);
    cudaGetSymbolAddress((void**)&dst, g_dst);
    cudaGetSymbolAddress((void**)&csr, g_csr);
    cudaGetSymbolAddress((void**)&deg, g_deg);
    cudaGetSymbolAddress((void**)&off, g_off);
    cudaGetSymbolAddress((void**)&cur, g_cur);

    const size_t mlp_smem = (size_t)(2 * DF * DF + 2 * TM * TLD) * sizeof(float);
    const size_t fc_smem  = (size_t)(DF * NCLS + FTM * DF + FTM * NCLS + 2 * FTM) * sizeof(float);
    cudaFuncSetAttribute(mlp_kernel, cudaFuncAttributeMaxDynamicSharedMemorySize, (int)mlp_smem);
    cudaFuncSetAttribute(fc_softmax_kernel, cudaFuncAttributeMaxDynamicSharedMemorySize, (int)fc_smem);

    const int egrid = (NEDGES + 255) / 256;
    const int ngrid = (NNODES + 255) / 256;
    const int agrid = (int)(((long long)NNODES * 32 + 255) / 256);
    const int mgrid = (NNODES + TM - 1) / TM;

    // --- CSR build (per launch; deterministic multiset per node) ---
    zero_int_kernel<<<ngrid, 256>>>(deg, NNODES);
    build_edges_kernel<<<egrid, 256>>>(ei_raw, src, dst, deg);
    scan_kernel<<<1, SCAN_T>>>(deg, off, cur);
    scatter_kernel<<<egrid, 256>>>(src, dst, cur, csr);

    // Layer 1
    agg_kernel<<<agrid, 256>>>(x, x, off, csr, pre);
    mlp_kernel<<<mgrid, 256, mlp_smem>>>(pre, w1a, b1a, w1b, b1b, h1);
    // Layer 2
    agg_kernel<<<agrid, 256>>>(h1, h1, off, csr, pre);
    mlp_kernel<<<mgrid, 256, mlp_smem>>>(pre, w2a, b2a, w2b, b2b, h2);
    // Head
    fc_softmax_kernel<<<mgrid, 320, fc_smem>>>(h2, wfc, bfc, out);
}

// round 4
// speedup vs baseline: 1.9918x; 1.2081x over previous
#include <cuda_runtime.h>

#define NNODES 100000
#define NEDGES 1600000
#define DF 128
#define NCLS 40
#define TM 128
#define TLD 132   // padded tile stride (floats)
#define FTM 64
#define SCAN_T 1024
#define SCAN_CHUNK ((NNODES + SCAN_T - 1) / SCAN_T)   // 98

// Scratch (allocation-free rule: __device__ globals)
__device__ float g_pre[NNODES * DF];
__device__ float g_h1[NNODES * DF];
__device__ float g_h2[NNODES * DF];
__device__ int   g_csr[NEDGES];
__device__ int   g_deg[NNODES];
__device__ int   g_off[NNODES + 1];
__device__ int   g_cur[NNODES];

// ---- packed f32x2 helpers ---------------------------------------------------
__device__ __forceinline__ unsigned long long pack2(float x, float y) {
    unsigned long long r;
    asm("mov.b64 %0, {%1,%2};" : "=l"(r)
        : "r"(__float_as_uint(x)), "r"(__float_as_uint(y)));
    return r;
}
__device__ __forceinline__ unsigned long long packdup(float x) {
    unsigned long long r;
    asm("mov.b64 %0, {%1,%1};" : "=l"(r) : "r"(__float_as_uint(x)));
    return r;
}
#define FMA2(d, a, b, c) \
    asm("fma.rn.f32x2 %0, %1, %2, %3;" : "=l"(d) : "l"(a), "l"(b), "l"(c))

__device__ __forceinline__ bool edges_are_i64(const int* raw) {
    return (raw[1] | raw[3] | raw[5] | raw[7] |
            raw[9] | raw[11] | raw[13] | raw[15]) == 0;
}

// ---------------------------------------------------------------------------
__global__ void zero_int_kernel(int* __restrict__ p, int n) {
    int i = blockIdx.x * blockDim.x + threadIdx.x;
    if (i < n) p[i] = 0;
}

// Degree histogram by dst, reading edge_index raw (int32/int64 robust).
__global__ void hist_kernel(const int* __restrict__ raw, int* __restrict__ deg) {
    bool is64 = edges_are_i64(raw);
    int i = blockIdx.x * blockDim.x + threadIdx.x;
    if (i >= NEDGES) return;
    int d = is64 ? raw[2 * NEDGES + 2 * i] : raw[NEDGES + i];
    atomicAdd(deg + d, 1);
}

// Single-block exclusive scan of degrees -> offsets (+ cursor copy).
__global__ __launch_bounds__(SCAN_T, 1)
void scan_kernel(const int* __restrict__ deg, int* __restrict__ off,
                 int* __restrict__ cur) {
    __shared__ int s[SCAN_T];
    int t = threadIdx.x;
    int base = t * SCAN_CHUNK;
    int sum = 0;
    for (int i = 0; i < SCAN_CHUNK; i++) {
        int idx = base + i;
        if (idx < NNODES) sum += deg[idx];
    }
    s[t] = sum;
    __syncthreads();
    for (int ofs = 1; ofs < SCAN_T; ofs <<= 1) {
        int v = (t >= ofs) ? s[t - ofs] : 0;
        __syncthreads();
        s[t] += v;
        __syncthreads();
    }
    int run = (t == 0) ? 0 : s[t - 1];
    for (int i = 0; i < SCAN_CHUNK; i++) {
        int idx = base + i;
        if (idx < NNODES) {
            off[idx] = run;
            cur[idx] = run;
            run += deg[idx];
        }
    }
    if (t == 0) off[NNODES] = s[SCAN_T - 1];
}

__global__ void scatter_kernel(const int* __restrict__ raw,
                               int* __restrict__ cur,
                               int* __restrict__ csr) {
    bool is64 = edges_are_i64(raw);
    int i = blockIdx.x * blockDim.x + threadIdx.x;
    if (i >= NEDGES) return;
    int s, d;
    if (is64) { s = raw[2 * i]; d = raw[2 * NEDGES + 2 * i]; }
    else      { s = raw[i];     d = raw[NEDGES + i]; }
    int pos = atomicAdd(cur + d, 1);
    csr[pos] = s;
}

// ---------------------------------------------------------------------------
// Gather aggregation, no atomics: pre[node] = xin[node] + sum_{nbr} feat[nbr].
// Warp per node, 32 lanes x float4 = 512B row, 8 rows in flight.
__global__ void agg_kernel(const float* __restrict__ feat,
                           const float* __restrict__ xin,
                           const int* __restrict__ off,
                           const int* __restrict__ csr,
                           float* __restrict__ pre) {
    int node = (blockIdx.x * blockDim.x + threadIdx.x) >> 5;
    int lane = threadIdx.x & 31;
    if (node >= NNODES) return;
    int e0 = off[node], e1 = off[node + 1];
    float4 acc = reinterpret_cast<const float4*>(xin + (size_t)node * DF)[lane];
    int e = e0;
#pragma unroll 1
    for (; e + 8 <= e1; e += 8) {
        int n[8];
#pragma unroll
        for (int j = 0; j < 8; j++) n[j] = __ldg(csr + e + j);
        float4 v[8];
#pragma unroll
        for (int j = 0; j < 8; j++)
            v[j] = *reinterpret_cast<const float4*>(feat + (size_t)n[j] * DF + lane * 4);
#pragma unroll
        for (int j = 0; j < 8; j++) {
            acc.x += v[j].x; acc.y += v[j].y; acc.z += v[j].z; acc.w += v[j].w;
        }
    }
    for (; e < e1; e++) {
        int n0 = __ldg(csr + e);
        float4 v0 = *reinterpret_cast<const float4*>(feat + (size_t)n0 * DF + lane * 4);
        acc.x += v0.x; acc.y += v0.y; acc.z += v0.z; acc.w += v0.w;
    }
    *reinterpret_cast<float4*>(pre + (size_t)node * DF + lane * 4) = acc;
}

// ---------------------------------------------------------------------------
// Fused GIN MLP with packed f32x2 FMA, 128-row tile, 256 threads:
// out = relu( relu( pre @ wa + ba ) @ wb + bb )
// Intermediate h written back into the input tile buffer (regs hold accs).
__global__ __launch_bounds__(256, 1)
void mlp_kernel(const float* __restrict__ pre,
                const float* __restrict__ wa, const float* __restrict__ ba,
                const float* __restrict__ wb, const float* __restrict__ bb,
                float* __restrict__ out) {
    extern __shared__ float sm[];
    float* ws_a = sm;                 // 128*128
    float* ws_b = sm + DF * DF;       // 128*128
    float* tile = sm + 2 * DF * DF;   // TM*TLD (input, then h)

    const int t = threadIdx.x;
    const int row0 = blockIdx.x * TM;

    // Load both weight matrices (k-major: w[k*128 + n])
    {
        const float4* wa4 = reinterpret_cast<const float4*>(wa);
        const float4* wb4 = reinterpret_cast<const float4*>(wb);
        float4* wsa4 = reinterpret_cast<float4*>(ws_a);
        float4* wsb4 = reinterpret_cast<float4*>(ws_b);
#pragma unroll
        for (int i = 0; i < (DF * DF / 4) / 256; i++) {
            wsa4[t + i * 256] = wa4[t + i * 256];
            wsb4[t + i * 256] = wb4[t + i * 256];
        }
    }

    // Load input tile (128 rows x 128 cols)
    {
        int c4 = t & 31;
        int rr = t >> 5;
#pragma unroll
        for (int i = 0; i < TM / 8; i++) {
            int r = rr + i * 8;
            int gr = row0 + r;
            float4 v = make_float4(0.f, 0.f, 0.f, 0.f);
            if (gr < NNODES)
                v = reinterpret_cast<const float4*>(pre + (size_t)gr * DF)[c4];
            *reinterpret_cast<float4*>(&tile[r * TLD + c4 * 4]) = v;
        }
    }
    __syncthreads();

    const int tx = t & 15;          // 16 column groups of 8
    const int ty = t >> 4;          // 16 row groups of 8
    const int col = tx * 8;
    const int rbase = ty * 8;

    unsigned long long acc[8][4];   // 8 rows x 4 packed pairs

    // ---- GEMM 1: h = relu(tile @ wa + ba) ----
    {
        float4 bv0 = *reinterpret_cast<const float4*>(ba + col);
        float4 bv1 = *reinterpret_cast<const float4*>(ba + col + 4);
        unsigned long long bp[4] = {pack2(bv0.x, bv0.y), pack2(bv0.z, bv0.w),
                                    pack2(bv1.x, bv1.y), pack2(bv1.z, bv1.w)};
#pragma unroll
        for (int i = 0; i < 8; i++)
#pragma unroll
            for (int j = 0; j < 4; j++) acc[i][j] = bp[j];
    }
#pragma unroll 2
    for (int k4 = 0; k4 < DF / 4; k4++) {
        const int k = k4 * 4;
        float a_[8][4];
#pragma unroll
        for (int i = 0; i < 8; i++) {
            float4 f = *reinterpret_cast<const float4*>(&tile[(rbase + i) * TLD + k]);
            a_[i][0] = f.x; a_[i][1] = f.y; a_[i][2] = f.z; a_[i][3] = f.w;
        }
#pragma unroll
        for (int kk = 0; kk < 4; kk++) {
            ulonglong2 q0 = *reinterpret_cast<const ulonglong2*>(&ws_a[(k + kk) * DF + col]);
            ulonglong2 q1 = *reinterpret_cast<const ulonglong2*>(&ws_a[(k + kk) * DF + col + 4]);
#pragma unroll
            for (int i = 0; i < 8; i++) {
                unsigned long long ap = packdup(a_[i][kk]);
                FMA2(acc[i][0], ap, q0.x, acc[i][0]);
                FMA2(acc[i][1], ap, q0.y, acc[i][1]);
                FMA2(acc[i][2], ap, q1.x, acc[i][2]);
                FMA2(acc[i][3], ap, q1.y, acc[i][3]);
            }
        }
    }
    __syncthreads();   // all reads of tile complete
#pragma unroll
    for (int i = 0; i < 8; i++) {
        float v[8];
#pragma unroll
        for (int j = 0; j < 4; j++) {
            uint2 u = *reinterpret_cast<uint2*>(&acc[i][j]);
            v[2 * j]     = fmaxf(__uint_as_float(u.x), 0.f);
            v[2 * j + 1] = fmaxf(__uint_as_float(u.y), 0.f);
        }
        *reinterpret_cast<float4*>(&tile[(rbase + i) * TLD + col]) =
            make_float4(v[0], v[1], v[2], v[3]);
        *reinterpret_cast<float4*>(&tile[(rbase + i) * TLD + col + 4]) =
            make_float4(v[4], v[5], v[6], v[7]);
    }
    __syncthreads();

    // ---- GEMM 2: out = relu(h @ wb + bb) ----
    {
        float4 bv0 = *reinterpret_cast<const float4*>(bb + col);
        float4 bv1 = *reinterpret_cast<const float4*>(bb + col + 4);
        unsigned long long bp[4] = {pack2(bv0.x, bv0.y), pack2(bv0.z, bv0.w),
                                    pack2(bv1.x, bv1.y), pack2(bv1.z, bv1.w)};
#pragma unroll
        for (int i = 0; i < 8; i++)
#pragma unroll
            for (int j = 0; j < 4; j++) acc[i][j] = bp[j];
    }
#pragma unroll 2
    for (int k4 = 0; k4 < DF / 4; k4++) {
        const int k = k4 * 4;
        float a_[8][4];
#pragma unroll
        for (int i = 0; i < 8; i++) {
            float4 f = *reinterpret_cast<const float4*>(&tile[(rbase + i) * TLD + k]);
            a_[i][0] = f.x; a_[i][1] = f.y; a_[i][2] = f.z; a_[i][3] = f.w;
        }
#pragma unroll
        for (int kk = 0; kk < 4; kk++) {
            ulonglong2 q0 = *reinterpret_cast<const ulonglong2*>(&ws_b[(k + kk) * DF + col]);
            ulonglong2 q1 = *reinterpret_cast<const ulonglong2*>(&ws_b[(k + kk) * DF + col + 4]);
#pragma unroll
            for (int i = 0; i < 8; i++) {
                unsigned long long ap = packdup(a_[i][kk]);
                FMA2(acc[i][0], ap, q0.x, acc[i][0]);
                FMA2(acc[i][1], ap, q0.y, acc[i][1]);
                FMA2(acc[i][2], ap, q1.x, acc[i][2]);
                FMA2(acc[i][3], ap, q1.y, acc[i][3]);
            }
        }
    }
#pragma unroll
    for (int i = 0; i < 8; i++) {
        int gr = row0 + rbase + i;
        if (gr >= NNODES) continue;
        float v[8];
#pragma unroll
        for (int j = 0; j < 4; j++) {
            uint2 u = *reinterpret_cast<uint2*>(&acc[i][j]);
            v[2 * j]     = fmaxf(__uint_as_float(u.x), 0.f);
            v[2 * j + 1] = fmaxf(__uint_as_float(u.y), 0.f);
        }
        *reinterpret_cast<float4*>(out + (size_t)gr * DF + col) =
            make_float4(v[0], v[1], v[2], v[3]);
        *reinterpret_cast<float4*>(out + (size_t)gr * DF + col + 4) =
            make_float4(v[4], v[5], v[6], v[7]);
    }
}

// ---------------------------------------------------------------------------
// Final FC (128 -> 40) + log_softmax, fused. 320 threads, 64 rows per block.
__global__ __launch_bounds__(320, 1)
void fc_softmax_kernel(const float* __restrict__ h, const float* __restrict__ wfc,
                       const float* __restrict__ bfc, float* __restrict__ out) {
    extern __shared__ float sm[];
    float* wsm   = sm;                         // DF*NCLS = 5120
    float* tile  = sm + DF * NCLS;             // FTM*DF  = 8192
    float* lg    = tile + FTM * DF;            // FTM*NCLS = 2560
    float* rstat = lg + FTM * NCLS;            // 2*FTM
    __shared__ float bsm[NCLS];

    const int t = threadIdx.x;
    const int row0 = blockIdx.x * FTM;

    for (int i = t; i < DF * NCLS; i += 320) wsm[i] = wfc[i];
    if (t < NCLS) bsm[t] = bfc[t];
    for (int i = t; i < FTM * DF / 4; i += 320) {
        int r = i >> 5;
        int c4 = i & 31;
        int gr = row0 + r;
        float4 v = (gr < NNODES)
                       ? reinterpret_cast<const float4*>(h + (size_t)gr * DF)[c4]
                       : make_float4(0.f, 0.f, 0.f, 0.f);
        reinterpret_cast<float4*>(tile)[i] = v;
    }
    __syncthreads();

    const int r = t / 5;
    const int cg = t % 5;
    const int cb = cg * 8;
    float acc[8];
#pragma unroll
    for (int j = 0; j < 8; j++) acc[j] = bsm[cb + j];
#pragma unroll 4
    for (int k = 0; k < DF; k++) {
        float a = tile[r * DF + k];
        float4 w0 = *reinterpret_cast<const float4*>(&wsm[k * NCLS + cb]);
        float4 w1 = *reinterpret_cast<const float4*>(&wsm[k * NCLS + cb + 4]);
        acc[0] += a * w0.x; acc[1] += a * w0.y; acc[2] += a * w0.z; acc[3] += a * w0.w;
        acc[4] += a * w1.x; acc[5] += a * w1.y; acc[6] += a * w1.z; acc[7] += a * w1.w;
    }
#pragma unroll
    for (int j = 0; j < 8; j++) lg[r * NCLS + cb + j] = acc[j];
    __syncthreads();

    if (t < FTM) {
        float m = -1e30f;
#pragma unroll
        for (int c = 0; c < NCLS; c++) m = fmaxf(m, lg[t * NCLS + c]);
        float s = 0.f;
#pragma unroll
        for (int c = 0; c < NCLS; c++) s += expf(lg[t * NCLS + c] - m);
        rstat[t] = m;
        rstat[FTM + t] = logf(s);
    }
    __syncthreads();

    int gr = row0 + r;
    if (gr < NNODES) {
        float m = rstat[r], ls = rstat[FTM + r];
#pragma unroll
        for (int j = 0; j < 8; j++)
            out[(size_t)gr * NCLS + cb + j] = lg[r * NCLS + cb + j] - m - ls;
    }
}

// ---------------------------------------------------------------------------
extern "C" void kernel_launch(void* const* d_in, const int* in_sizes, int n_in,
                              void* d_out, int out_size) {
    const float* x        = (const float*)d_in[0];
    const int*   ei_raw   = (const int*)d_in[1];
    const float* w1a      = (const float*)d_in[2];
    const float* b1a      = (const float*)d_in[3];
    const float* w1b      = (const float*)d_in[4];
    const float* b1b      = (const float*)d_in[5];
    const float* w2a      = (const float*)d_in[6];
    const float* b2a      = (const float*)d_in[7];
    const float* w2b      = (const float*)d_in[8];
    const float* b2b      = (const float*)d_in[9];
    const float* wfc      = (const float*)d_in[10];
    const float* bfc      = (const float*)d_in[11];
    float* out            = (float*)d_out;

    float *pre, *h1, *h2;
    int *csr, *deg, *off, *cur;
    cudaGetSymbolAddress((void**)&pre, g_pre);
    cudaGetSymbolAddress((void**)&h1, g_h1);
    cudaGetSymbolAddress((void**)&h2, g_h2);
    cudaGetSymbolAddress((void**)&csr, g_csr);
    cudaGetSymbolAddress((void**)&deg, g_deg);
    cudaGetSymbolAddress((void**)&off, g_off);
    cudaGetSymbolAddress((void**)&cur, g_cur);

    const size_t mlp_smem = (size_t)(2 * DF * DF + TM * TLD) * sizeof(float);
    const size_t fc_smem  = (size_t)(DF * NCLS + FTM * DF + FTM * NCLS + 2 * FTM) * sizeof(float);
    cudaFuncSetAttribute(mlp_kernel, cudaFuncAttributeMaxDynamicSharedMemorySize, (int)mlp_smem);
    cudaFuncSetAttribute(fc_softmax_kernel, cudaFuncAttributeMaxDynamicSharedMemorySize, (int)fc_smem);

    const int egrid = (NEDGES + 255) / 256;
    const int ngrid = (NNODES + 255) / 256;
    const int agrid = (int)(((long long)NNODES * 32 + 255) / 256);
    const int mgrid = (NNODES + TM - 1) / TM;
    const int fgrid = (NNODES + FTM - 1) / FTM;

    // --- CSR build ---
    zero_int_kernel<<<ngrid, 256>>>(deg, NNODES);
    hist_kernel<<<egrid, 256>>>(ei_raw, deg);
    scan_kernel<<<1, SCAN_T>>>(deg, off, cur);
    scatter_kernel<<<egrid, 256>>>(ei_raw, cur, csr);

    // Layer 1
    agg_kernel<<<agrid, 256>>>(x, x, off, csr, pre);
    mlp_kernel<<<mgrid, 256, mlp_smem>>>(pre, w1a, b1a, w1b, b1b, h1);
    // Layer 2
    agg_kernel<<<agrid, 256>>>(h1, h1, off, csr, pre);
    mlp_kernel<<<mgrid, 256, mlp_smem>>>(pre, w2a, b2a, w2b, b2b, h2);
    // Head
    fc_softmax_kernel<<<fgrid, 320, fc_smem>>>(h2, wfc, bfc, out);
}